// round 15
// baseline (speedup 1.0000x reference)
#include <cuda_runtime.h>
#include <cuda_fp16.h>
#include <cstdint>
#include <cstddef>

#define DIM    2048
#define BATCH  16384
#define TM     128          // == ghost-BN virtual batch
#define TN     128
#define KC     64           // K elems per chunk (fp16: 128B per row)
#define NCH    (DIM / KC)   // 32
#define NSTAGE 3
#define NTHR   512          // 16 warps, warp grid 4x4, warp tile 32x32

// smem per-stage layout (bytes): fp16 tiles, 144B row stride (128B data + 16 pad)
#define ROWB   144
#define ST_A   0
#define ST_B   (ST_A + TM * ROWB)            // 18432
#define STAGE_SZ (ST_B + TN * ROWB)          // 36864
#define SMEM_TOTAL (NSTAGE * STAGE_SZ)       // 110592  (2 CTAs/SM: 221184 <= 228KB)

// epilogue staging (reuses pipeline smem): [128][130] fp32 + stats
#define C_STRIDE 130
#define C_BYTES  (TM * C_STRIDE * 4)         // 66560
#define OFF_SUM  C_BYTES                     // 512 floats
#define OFF_SQ   (OFF_SUM + 2048)            // 512 floats

// ---------------- scratch ----------------
__device__ float g_x[(size_t)BATCH * DIM];              // z = BN(x) * priors
__device__ uint2 g_a[(size_t)BATCH * DIM / 4];          // feat (fp16 x4)
__device__ uint2 g_b[(size_t)DIM * DIM / 4];            // W (fp16 x4)

// ---------------- helpers ----------------
__device__ __forceinline__ uint32_t smem_u32(const void* p) {
    uint32_t a;
    asm("{ .reg .u64 t; cvta.to.shared.u64 t, %1; cvt.u32.u64 %0, t; }" : "=r"(a) : "l"(p));
    return a;
}

__device__ __forceinline__ void ldsm_x4(uint32_t* r, uint32_t addr) {
    asm volatile("ldmatrix.sync.aligned.m8n8.x4.shared.b16 {%0,%1,%2,%3}, [%4];"
                 : "=r"(r[0]), "=r"(r[1]), "=r"(r[2]), "=r"(r[3]) : "r"(addr));
}

__device__ __forceinline__ void mma_f16(float* c, const uint32_t* a, uint32_t b0, uint32_t b1) {
    asm volatile("mma.sync.aligned.m16n8k16.row.col.f32.f16.f16.f32 "
                 "{%0,%1,%2,%3}, {%4,%5,%6,%7}, {%8,%9}, {%0,%1,%2,%3};"
                 : "+f"(c[0]), "+f"(c[1]), "+f"(c[2]), "+f"(c[3])
                 : "r"(a[0]), "r"(a[1]), "r"(a[2]), "r"(a[3]), "r"(b0), "r"(b1));
}

__device__ __forceinline__ void cp16(uint32_t dst, const void* src) {
    asm volatile("cp.async.cg.shared.global [%0], [%1], 16;" :: "r"(dst), "l"(src));
}
#define CP_COMMIT() asm volatile("cp.async.commit_group;" ::: "memory")
#define CP_WAIT1()  asm volatile("cp.async.wait_group 1;" ::: "memory")

__device__ __forceinline__ uint32_t h2u(__half2 h) {
    return *reinterpret_cast<uint32_t*>(&h);
}

// ================= kernel 0: fp32 -> fp16 RN =================
#define FEAT_N4 ((BATCH * DIM) / 4)
#define W_N4    ((DIM * DIM) / 4)

__global__ void __launch_bounds__(256)
split_kernel(const float* __restrict__ feat, const float* __restrict__ wmat)
{
    int idx = blockIdx.x * 256 + threadIdx.x;
    if (idx < FEAT_N4) {
        float4 v = reinterpret_cast<const float4*>(feat)[idx];
        g_a[idx] = make_uint2(h2u(__floats2half2_rn(v.x, v.y)), h2u(__floats2half2_rn(v.z, v.w)));
    } else if (idx < FEAT_N4 + W_N4) {
        int j = idx - FEAT_N4;
        float4 v = reinterpret_cast<const float4*>(wmat)[j];
        g_b[j] = make_uint2(h2u(__floats2half2_rn(v.x, v.y)), h2u(__floats2half2_rn(v.z, v.w)));
    }
}

// ================= kernel 1: GEMM (fp16) + fused GhostBN + x priors =================
__global__ void __launch_bounds__(NTHR, 2)
gemm_bn_kernel(const float* __restrict__ gamma, const float* __restrict__ beta,
               const float* __restrict__ priors)
{
    extern __shared__ __align__(16) char smem[];
    const uint32_t sbase = smem_u32(smem);
    const int tid  = threadIdx.x;
    const int lane = tid & 31;
    const int wid  = tid >> 5;          // 0..15
    const int wm   = wid >> 2;          // warp row 0..3 (32 rows each)
    const int wn   = wid & 3;           // warp col 0..3 (32 cols each)
    const int m0   = blockIdx.y * TM;
    const int n0   = blockIdx.x * TN;

    // per-thread cp.async coordinates (16B chunks; 128B per tile row)
    // A tile: 128 rows x 8 chunks = 1024 -> 2/thread ; B tile same
    const char* pA[2]; const char* pB[2]; uint32_t dC[2];
    #pragma unroll
    for (int i = 0; i < 2; ++i) {
        int item = tid + i * NTHR, r = item >> 3, q = item & 7;
        pA[i] = (const char*)g_a + ((size_t)(m0 + r) * DIM + q * 8) * 2;
        pB[i] = (const char*)g_b + ((size_t)(n0 + r) * DIM + q * 8) * 2;
        dC[i] = (uint32_t)(r * ROWB + q * 16);
    }

    float acc[2][4][4];
    #pragma unroll
    for (int i = 0; i < 2; ++i)
        #pragma unroll
        for (int j = 0; j < 4; ++j)
            #pragma unroll
            for (int k = 0; k < 4; ++k) acc[i][j][k] = 0.f;

    // per-lane ldmatrix offsets (within a stage)
    const uint32_t a_off = (uint32_t)((wm * 32 + (lane & 15)) * ROWB + (lane >> 4) * 16);
    const uint32_t b_off = (uint32_t)((wn * 32 + (lane & 7) + ((lane >> 4) & 1) * 8) * ROWB
                                      + ((lane >> 3) & 1) * 16);

    // prologue: stages 0,1 in flight
    #pragma unroll
    for (int s = 0; s < 2; ++s) {
        const size_t kb = (size_t)(s * KC) * 2;   // byte offset along K
        const uint32_t sb = sbase + s * STAGE_SZ;
        #pragma unroll
        for (int i = 0; i < 2; ++i) cp16(sb + ST_A + dC[i], pA[i] + kb);
        #pragma unroll
        for (int i = 0; i < 2; ++i) cp16(sb + ST_B + dC[i], pB[i] + kb);
        CP_COMMIT();
    }

    int s_cur = 0, s_nxt = 2;
    for (int c = 0; c < NCH; ++c) {
        CP_WAIT1();
        __syncthreads();                          // stage s_cur ready; stage s_nxt free

        if (c + 2 < NCH) {
            const size_t kb = (size_t)((c + 2) * KC) * 2;
            const uint32_t sb = sbase + s_nxt * STAGE_SZ;
            #pragma unroll
            for (int i = 0; i < 2; ++i) cp16(sb + ST_A + dC[i], pA[i] + kb);
            #pragma unroll
            for (int i = 0; i < 2; ++i) cp16(sb + ST_B + dC[i], pB[i] + kb);
        }
        CP_COMMIT();

        const uint32_t st = sbase + s_cur * STAGE_SZ;
        #pragma unroll
        for (int ks = 0; ks < 4; ++ks) {
            const uint32_t kb = (uint32_t)(ks * 32);
            uint32_t af[2][4], bb[2][4];
            #pragma unroll
            for (int mt = 0; mt < 2; ++mt) ldsm_x4(af[mt], st + ST_A + a_off + mt * (16 * ROWB) + kb);
            #pragma unroll
            for (int bt = 0; bt < 2; ++bt) ldsm_x4(bb[bt], st + ST_B + b_off + bt * (16 * ROWB) + kb);
            #pragma unroll
            for (int mt = 0; mt < 2; ++mt)
                #pragma unroll
                for (int nt = 0; nt < 4; ++nt)
                    mma_f16(acc[mt][nt], af[mt], bb[nt >> 1][(nt & 1) * 2], bb[nt >> 1][(nt & 1) * 2 + 1]);
        }
        s_cur = (s_cur + 1) % NSTAGE;
        s_nxt = (s_nxt + 1) % NSTAGE;
    }
    __syncthreads();    // pipeline smem free; reuse for epilogue

    // ---- stage C tile to smem ----
    float* sf = reinterpret_cast<float*>(smem);           // [128][130]
    {
        const int rbase = wm * 32 + (lane >> 2);
        const int cbase = wn * 32 + (lane & 3) * 2;
        #pragma unroll
        for (int mt = 0; mt < 2; ++mt)
            #pragma unroll
            for (int nt = 0; nt < 4; ++nt) {
                int r = rbase + mt * 16, cc = cbase + nt * 8;
                *reinterpret_cast<float2*>(&sf[r * C_STRIDE + cc]) =
                    make_float2(acc[mt][nt][0], acc[mt][nt][1]);
                *reinterpret_cast<float2*>(&sf[(r + 8) * C_STRIDE + cc]) =
                    make_float2(acc[mt][nt][2], acc[mt][nt][3]);
            }
    }
    __syncthreads();

    // ---- ghost-BN stats over the 128-row tile (per column) ----
    float* s_sum = reinterpret_cast<float*>(smem + OFF_SUM);          // [512]
    float* s_sq  = reinterpret_cast<float*>(smem + OFF_SQ);           // [512]
    {
        const int col = tid & 127, part = tid >> 7;       // 4 partitions x 32 rows
        float sum = 0.f, sq = 0.f;
        #pragma unroll 8
        for (int r = part * 32; r < part * 32 + 32; ++r) {
            float v = sf[r * C_STRIDE + col];
            sum += v; sq += v * v;
        }
        s_sum[tid] = sum; s_sq[tid] = sq;
    }
    __syncthreads();
    if (tid < 128) {
        float sum = s_sum[tid] + s_sum[tid + 128] + s_sum[tid + 256] + s_sum[tid + 384];
        float sq  = s_sq[tid] + s_sq[tid + 128] + s_sq[tid + 256] + s_sq[tid + 384];
        float mean = sum * (1.f / 128.f);
        float var  = fmaxf(sq * (1.f / 128.f) - mean * mean, 0.f);
        float sc = gamma[n0 + tid] * rsqrtf(var + 1e-5f);
        s_sum[tid] = sc;                         // scale
        s_sq[tid]  = beta[n0 + tid] - mean * sc; // shift
    }
    __syncthreads();

    // ---- normalized write x priors (float4) ----
    float* orow = g_x + (size_t)m0 * DIM + n0;
    const float* prow = priors + (size_t)m0 * DIM + n0;
    #pragma unroll
    for (int i = 0; i < 8; ++i) {
        int idx = tid + i * NTHR;                // 4096 float4s
        int r = idx >> 5, c4 = (idx & 31) * 4;
        float4 p = *reinterpret_cast<const float4*>(&prow[(size_t)r * DIM + c4]);
        float4 v;
        v.x = (sf[r * C_STRIDE + c4 + 0] * s_sum[c4 + 0] + s_sq[c4 + 0]) * p.x;
        v.y = (sf[r * C_STRIDE + c4 + 1] * s_sum[c4 + 1] + s_sq[c4 + 1]) * p.y;
        v.z = (sf[r * C_STRIDE + c4 + 2] * s_sum[c4 + 2] + s_sq[c4 + 2]) * p.z;
        v.w = (sf[r * C_STRIDE + c4 + 3] * s_sum[c4 + 3] + s_sq[c4 + 3]) * p.w;
        *reinterpret_cast<float4*>(&orow[(size_t)r * DIM + c4]) = v;
    }
}

// ================= kernel 2: sparsemax (warm-started Michelot, warp-per-row) =================
__device__ __forceinline__ float warp_sum(float v) {
    #pragma unroll
    for (int o = 16; o > 0; o >>= 1) v += __shfl_xor_sync(0xffffffffu, v, o);
    return v;
}
__device__ __forceinline__ float warp_max(float v) {
    #pragma unroll
    for (int o = 16; o > 0; o >>= 1) v = fmaxf(v, __shfl_xor_sync(0xffffffffu, v, o));
    return v;
}

__global__ void __launch_bounds__(256)
sparsemax_kernel(float* __restrict__ out)
{
    const int lane = threadIdx.x & 31;
    const int row  = blockIdx.x * 8 + (threadIdx.x >> 5);
    const float4* x4 = reinterpret_cast<const float4*>(g_x + (size_t)row * DIM);

    float z[64];
    float s = 0.f, mx = -1e30f;
    #pragma unroll
    for (int i = 0; i < 16; ++i) {
        float4 a = x4[lane + i * 32];
        z[i * 4 + 0] = a.x; z[i * 4 + 1] = a.y; z[i * 4 + 2] = a.z; z[i * 4 + 3] = a.w;
        s += a.x + a.y + a.z + a.w;
        mx = fmaxf(mx, fmaxf(fmaxf(a.x, a.y), fmaxf(a.z, a.w)));
    }
    s  = warp_sum(s);
    mx = warp_max(mx);
    // warm start: tau* in [max-1, max-1/D]; both candidates are valid lower bounds
    float tau = fmaxf(mx - 1.f, (s - 1.f) * (1.f / (float)DIM));

    for (int it = 0; it < 32; ++it) {
        float ps = 0.f, pc = 0.f;
        #pragma unroll
        for (int i = 0; i < 64; ++i)
            if (z[i] > tau) { ps += z[i]; pc += 1.f; }
        ps = warp_sum(ps); pc = warp_sum(pc);
        float tn = (ps - 1.f) / pc;
        if (tn == tau) break;        // warp-uniform (same reduced values)
        tau = tn;
    }

    float4* o4 = reinterpret_cast<float4*>(out + (size_t)row * DIM);
    #pragma unroll
    for (int i = 0; i < 16; ++i) {
        float4 v;
        v.x = fmaxf(z[i * 4 + 0] - tau, 0.f);
        v.y = fmaxf(z[i * 4 + 1] - tau, 0.f);
        v.z = fmaxf(z[i * 4 + 2] - tau, 0.f);
        v.w = fmaxf(z[i * 4 + 3] - tau, 0.f);
        o4[lane + i * 32] = v;
    }
}

// ================= launch =================
extern "C" void kernel_launch(void* const* d_in, const int* in_sizes, int n_in,
                              void* d_out, int out_size)
{
    const float* priors = (const float*)d_in[0];
    const float* feat   = (const float*)d_in[1];
    const float* fw     = (const float*)d_in[2];
    const float* gamma  = (const float*)d_in[3];
    const float* beta   = (const float*)d_in[4];
    float* out = (float*)d_out;

    static bool attr_set = false;
    if (!attr_set) {
        cudaFuncSetAttribute(gemm_bn_kernel, cudaFuncAttributeMaxDynamicSharedMemorySize, SMEM_TOTAL);
        attr_set = true;
    }

    split_kernel<<<(FEAT_N4 + W_N4 + 255) / 256, 256>>>(feat, fw);
    dim3 grid(DIM / TN, BATCH / TM);    // (16, 128); x fastest keeps W in L2
    gemm_bn_kernel<<<grid, NTHR, SMEM_TOTAL>>>(gamma, beta, priors);
    sparsemax_kernel<<<BATCH / 8, 256>>>(out);
}

// round 16
// speedup vs baseline: 1.0252x; 1.0252x over previous
#include <cuda_runtime.h>
#include <cuda_fp16.h>
#include <cstdint>
#include <cstddef>

#define DIM    2048
#define BATCH  16384
#define TM     128          // == ghost-BN virtual batch
#define TN     128
#define KC     64           // K elems per chunk (fp16: 128B per row)
#define NCH    (DIM / KC)   // 32
#define NSTAGE 3
#define NTHR   256

// smem per-stage layout (bytes): fp16 tiles, 144B row stride (128B data + 16 pad)
#define ROWB   144
#define ST_A   0
#define ST_B   (ST_A + TM * ROWB)            // 18432
#define STAGE_SZ (ST_B + TN * ROWB)          // 36864
#define SMEM_TOTAL (NSTAGE * STAGE_SZ)       // 110592  (2 CTAs/SM: 221184 <= 228KB)

// epilogue staging (reuses pipeline smem): [128][130] fp32 + stats
#define C_STRIDE 130
#define C_BYTES  (TM * C_STRIDE * 4)         // 66560
#define OFF_SUM  C_BYTES                     // 256 floats
#define OFF_SQ   (OFF_SUM + 1024)            // 256 floats

// ---------------- scratch ----------------
__device__ float g_x[(size_t)BATCH * DIM];              // z = BN(x) * priors
__device__ uint2 g_a[(size_t)BATCH * DIM / 4];          // feat (fp16 x4)
__device__ uint2 g_b[(size_t)DIM * DIM / 4];            // W (fp16 x4)

// ---------------- helpers ----------------
__device__ __forceinline__ uint32_t smem_u32(const void* p) {
    uint32_t a;
    asm("{ .reg .u64 t; cvta.to.shared.u64 t, %1; cvt.u32.u64 %0, t; }" : "=r"(a) : "l"(p));
    return a;
}

__device__ __forceinline__ void ldsm_x4(uint32_t* r, uint32_t addr) {
    asm volatile("ldmatrix.sync.aligned.m8n8.x4.shared.b16 {%0,%1,%2,%3}, [%4];"
                 : "=r"(r[0]), "=r"(r[1]), "=r"(r[2]), "=r"(r[3]) : "r"(addr));
}

__device__ __forceinline__ void mma_f16(float* c, const uint32_t* a, uint32_t b0, uint32_t b1) {
    asm volatile("mma.sync.aligned.m16n8k16.row.col.f32.f16.f16.f32 "
                 "{%0,%1,%2,%3}, {%4,%5,%6,%7}, {%8,%9}, {%0,%1,%2,%3};"
                 : "+f"(c[0]), "+f"(c[1]), "+f"(c[2]), "+f"(c[3])
                 : "r"(a[0]), "r"(a[1]), "r"(a[2]), "r"(a[3]), "r"(b0), "r"(b1));
}

__device__ __forceinline__ void cp16(uint32_t dst, const void* src) {
    asm volatile("cp.async.cg.shared.global [%0], [%1], 16;" :: "r"(dst), "l"(src));
}
#define CP_COMMIT() asm volatile("cp.async.commit_group;" ::: "memory")
#define CP_WAIT1()  asm volatile("cp.async.wait_group 1;" ::: "memory")

__device__ __forceinline__ uint32_t h2u(__half2 h) {
    return *reinterpret_cast<uint32_t*>(&h);
}

// ================= kernel 0: fp32 -> fp16 RN =================
#define FEAT_N4 ((BATCH * DIM) / 4)
#define W_N4    ((DIM * DIM) / 4)

__global__ void __launch_bounds__(256)
split_kernel(const float* __restrict__ feat, const float* __restrict__ wmat)
{
    int idx = blockIdx.x * 256 + threadIdx.x;
    if (idx < FEAT_N4) {
        float4 v = reinterpret_cast<const float4*>(feat)[idx];
        g_a[idx] = make_uint2(h2u(__floats2half2_rn(v.x, v.y)), h2u(__floats2half2_rn(v.z, v.w)));
    } else if (idx < FEAT_N4 + W_N4) {
        int j = idx - FEAT_N4;
        float4 v = reinterpret_cast<const float4*>(wmat)[j];
        g_b[j] = make_uint2(h2u(__floats2half2_rn(v.x, v.y)), h2u(__floats2half2_rn(v.z, v.w)));
    }
}

// ================= kernel 1: GEMM (fp16) + fused GhostBN + x priors (R13 form) =================
__global__ void __launch_bounds__(NTHR, 2)
gemm_bn_kernel(const float* __restrict__ gamma, const float* __restrict__ beta,
               const float* __restrict__ priors)
{
    extern __shared__ __align__(16) char smem[];
    const uint32_t sbase = smem_u32(smem);
    const int tid  = threadIdx.x;
    const int lane = tid & 31;
    const int wid  = tid >> 5;          // 0..7
    const int wm   = wid >> 2;          // warp row 0..1 (64 rows each)
    const int wn   = wid & 3;           // warp col 0..3 (32 cols each)
    const int m0   = blockIdx.y * TM;
    const int n0   = blockIdx.x * TN;

    // per-thread cp.async coordinates (16B chunks; 128B per tile row)
    const char* pA[4]; uint32_t dA[4];
    const char* pB[4]; uint32_t dB[4];
    #pragma unroll
    for (int i = 0; i < 4; ++i) {
        int item = tid + i * NTHR, r = item >> 3, q = item & 7;
        pA[i] = (const char*)g_a + ((size_t)(m0 + r) * DIM + q * 8) * 2;
        pB[i] = (const char*)g_b + ((size_t)(n0 + r) * DIM + q * 8) * 2;
        dA[i] = (uint32_t)(r * ROWB + q * 16);
        dB[i] = dA[i];
    }

    float acc[4][4][4];
    #pragma unroll
    for (int i = 0; i < 4; ++i)
        #pragma unroll
        for (int j = 0; j < 4; ++j)
            #pragma unroll
            for (int k = 0; k < 4; ++k) acc[i][j][k] = 0.f;

    // per-lane ldmatrix offsets (within a stage)
    const uint32_t a_off = (uint32_t)((wm * 64 + (lane & 15)) * ROWB + (lane >> 4) * 16);
    const uint32_t b_off = (uint32_t)((wn * 32 + (lane & 7) + ((lane >> 4) & 1) * 8) * ROWB
                                      + ((lane >> 3) & 1) * 16);

    // prologue: stages 0,1 in flight
    #pragma unroll
    for (int s = 0; s < 2; ++s) {
        const size_t kb = (size_t)(s * KC) * 2;   // byte offset along K
        const uint32_t sb = sbase + s * STAGE_SZ;
        #pragma unroll
        for (int i = 0; i < 4; ++i) cp16(sb + ST_A + dA[i], pA[i] + kb);
        #pragma unroll
        for (int i = 0; i < 4; ++i) cp16(sb + ST_B + dB[i], pB[i] + kb);
        CP_COMMIT();
    }

    int s_cur = 0, s_nxt = 2;
    for (int c = 0; c < NCH; ++c) {
        CP_WAIT1();
        __syncthreads();                          // stage s_cur ready; stage s_nxt free

        if (c + 2 < NCH) {
            const size_t kb = (size_t)((c + 2) * KC) * 2;
            const uint32_t sb = sbase + s_nxt * STAGE_SZ;
            #pragma unroll
            for (int i = 0; i < 4; ++i) cp16(sb + ST_A + dA[i], pA[i] + kb);
            #pragma unroll
            for (int i = 0; i < 4; ++i) cp16(sb + ST_B + dB[i], pB[i] + kb);
        }
        CP_COMMIT();

        const uint32_t st = sbase + s_cur * STAGE_SZ;
        #pragma unroll
        for (int ks = 0; ks < 4; ++ks) {
            const uint32_t kb = (uint32_t)(ks * 32);
            uint32_t af[4][4], bb[2][4];
            #pragma unroll
            for (int mt = 0; mt < 4; ++mt) ldsm_x4(af[mt], st + ST_A + a_off + mt * (16 * ROWB) + kb);
            #pragma unroll
            for (int bt = 0; bt < 2; ++bt) ldsm_x4(bb[bt], st + ST_B + b_off + bt * (16 * ROWB) + kb);
            #pragma unroll
            for (int mt = 0; mt < 4; ++mt)
                #pragma unroll
                for (int nt = 0; nt < 4; ++nt)
                    mma_f16(acc[mt][nt], af[mt], bb[nt >> 1][(nt & 1) * 2], bb[nt >> 1][(nt & 1) * 2 + 1]);
        }
        s_cur = (s_cur + 1) % NSTAGE;
        s_nxt = (s_nxt + 1) % NSTAGE;
    }
    __syncthreads();    // pipeline smem free; reuse for epilogue

    // ---- stage C tile to smem ----
    float* sf = reinterpret_cast<float*>(smem);           // [128][130]
    {
        const int rbase = wm * 64 + (lane >> 2);
        const int cbase = wn * 32 + (lane & 3) * 2;
        #pragma unroll
        for (int mt = 0; mt < 4; ++mt)
            #pragma unroll
            for (int nt = 0; nt < 4; ++nt) {
                int r = rbase + mt * 16, cc = cbase + nt * 8;
                *reinterpret_cast<float2*>(&sf[r * C_STRIDE + cc]) =
                    make_float2(acc[mt][nt][0], acc[mt][nt][1]);
                *reinterpret_cast<float2*>(&sf[(r + 8) * C_STRIDE + cc]) =
                    make_float2(acc[mt][nt][2], acc[mt][nt][3]);
            }
    }
    __syncthreads();

    // ---- ghost-BN stats over the 128-row tile (per column) ----
    float* s_sum = reinterpret_cast<float*>(smem + OFF_SUM);          // [256]
    float* s_sq  = reinterpret_cast<float*>(smem + OFF_SQ);           // [256]
    {
        const int col = tid & 127, part = tid >> 7;       // 2 partitions x 64 rows
        float sum = 0.f, sq = 0.f;
        #pragma unroll 8
        for (int r = part * 64; r < part * 64 + 64; ++r) {
            float v = sf[r * C_STRIDE + col];
            sum += v; sq += v * v;
        }
        s_sum[tid] = sum; s_sq[tid] = sq;
    }
    __syncthreads();
    if (tid < 128) {
        float sum = s_sum[tid] + s_sum[tid + 128];
        float sq  = s_sq[tid] + s_sq[tid + 128];
        float mean = sum * (1.f / 128.f);
        float var  = fmaxf(sq * (1.f / 128.f) - mean * mean, 0.f);
        float sc = gamma[n0 + tid] * rsqrtf(var + 1e-5f);
        s_sum[tid] = sc;                         // scale
        s_sq[tid]  = beta[n0 + tid] - mean * sc; // shift
    }
    __syncthreads();

    // ---- normalized write x priors (float4) ----
    float* orow = g_x + (size_t)m0 * DIM + n0;
    const float* prow = priors + (size_t)m0 * DIM + n0;
    #pragma unroll
    for (int i = 0; i < 16; ++i) {
        int idx = tid + i * NTHR;                // 4096 float4s
        int r = idx >> 5, c4 = (idx & 31) * 4;
        float4 p = *reinterpret_cast<const float4*>(&prow[(size_t)r * DIM + c4]);
        float4 v;
        v.x = (sf[r * C_STRIDE + c4 + 0] * s_sum[c4 + 0] + s_sq[c4 + 0]) * p.x;
        v.y = (sf[r * C_STRIDE + c4 + 1] * s_sum[c4 + 1] + s_sq[c4 + 1]) * p.y;
        v.z = (sf[r * C_STRIDE + c4 + 2] * s_sum[c4 + 2] + s_sq[c4 + 2]) * p.z;
        v.w = (sf[r * C_STRIDE + c4 + 3] * s_sum[c4 + 3] + s_sq[c4 + 3]) * p.w;
        *reinterpret_cast<float4*>(&orow[(size_t)r * DIM + c4]) = v;
    }
}

// ================= kernel 2: sparsemax (2 warps per row, warm-started Michelot) =================
__device__ __forceinline__ float warp_sum(float v) {
    #pragma unroll
    for (int o = 16; o > 0; o >>= 1) v += __shfl_xor_sync(0xffffffffu, v, o);
    return v;
}
__device__ __forceinline__ float warp_max(float v) {
    #pragma unroll
    for (int o = 16; o > 0; o >>= 1) v = fmaxf(v, __shfl_xor_sync(0xffffffffu, v, o));
    return v;
}

__global__ void __launch_bounds__(256)
sparsemax_kernel(float* __restrict__ out)
{
    __shared__ float2 red[8];     // per-warp (sum, count) or (sum, max)
    const int tid  = threadIdx.x;
    const int lane = tid & 31;
    const int wid  = tid >> 5;            // 0..7
    const int rloc = wid >> 1;            // row within block 0..3
    const int half = wid & 1;             // which half of the row
    const int row  = blockIdx.x * 4 + rloc;
    const float4* x4 = reinterpret_cast<const float4*>(g_x + (size_t)row * DIM);

    // this half-warp-pair covers float4 indices: lane + half*32 + i*64, i<8
    float z[32];
    float s = 0.f, mx = -1e30f;
    #pragma unroll
    for (int i = 0; i < 8; ++i) {
        float4 a = x4[lane + half * 32 + i * 64];
        z[i * 4 + 0] = a.x; z[i * 4 + 1] = a.y; z[i * 4 + 2] = a.z; z[i * 4 + 3] = a.w;
        s += a.x + a.y + a.z + a.w;
        mx = fmaxf(mx, fmaxf(fmaxf(a.x, a.y), fmaxf(a.z, a.w)));
    }
    s  = warp_sum(s);
    mx = warp_max(mx);
    if (lane == 0) red[wid] = make_float2(s, mx);
    __syncthreads();
    {
        float2 a = red[rloc * 2], b = red[rloc * 2 + 1];
        s  = a.x + b.x;
        mx = fmaxf(a.y, b.y);
    }
    __syncthreads();
    // warm start: tau* in [max-1, max-1/D]; both candidates are valid lower bounds
    float tau = fmaxf(mx - 1.f, (s - 1.f) * (1.f / (float)DIM));

    for (int it = 0; it < 32; ++it) {
        float ps = 0.f, pc = 0.f;
        #pragma unroll
        for (int i = 0; i < 32; ++i)
            if (z[i] > tau) { ps += z[i]; pc += 1.f; }
        ps = warp_sum(ps); pc = warp_sum(pc);
        if (lane == 0) red[wid] = make_float2(ps, pc);
        __syncthreads();
        float2 a = red[rloc * 2], b = red[rloc * 2 + 1];
        float tn = (a.x + b.x - 1.f) / (a.y + b.y);
        __syncthreads();
        bool done = (tn == tau);
        tau = tn;
        if (__syncthreads_and(done)) break;   // all 4 rows converged
    }

    float4* o4 = reinterpret_cast<float4*>(out + (size_t)row * DIM);
    #pragma unroll
    for (int i = 0; i < 8; ++i) {
        float4 v;
        v.x = fmaxf(z[i * 4 + 0] - tau, 0.f);
        v.y = fmaxf(z[i * 4 + 1] - tau, 0.f);
        v.z = fmaxf(z[i * 4 + 2] - tau, 0.f);
        v.w = fmaxf(z[i * 4 + 3] - tau, 0.f);
        o4[lane + half * 32 + i * 64] = v;
    }
}

// ================= launch =================
extern "C" void kernel_launch(void* const* d_in, const int* in_sizes, int n_in,
                              void* d_out, int out_size)
{
    const float* priors = (const float*)d_in[0];
    const float* feat   = (const float*)d_in[1];
    const float* fw     = (const float*)d_in[2];
    const float* gamma  = (const float*)d_in[3];
    const float* beta   = (const float*)d_in[4];
    float* out = (float*)d_out;

    static bool attr_set = false;
    if (!attr_set) {
        cudaFuncSetAttribute(gemm_bn_kernel, cudaFuncAttributeMaxDynamicSharedMemorySize, SMEM_TOTAL);
        attr_set = true;
    }

    split_kernel<<<(FEAT_N4 + W_N4 + 255) / 256, 256>>>(feat, fw);
    dim3 grid(DIM / TN, BATCH / TM);    // (16, 128); x fastest keeps W in L2
    gemm_bn_kernel<<<grid, NTHR, SMEM_TOTAL>>>(gamma, beta, priors);
    sparsemax_kernel<<<BATCH / 4, 256>>>(out);
}

// round 17
// speedup vs baseline: 1.0449x; 1.0192x over previous
#include <cuda_runtime.h>
#include <cuda_fp16.h>
#include <cstdint>
#include <cstddef>

#define DIM    2048
#define BATCH  16384
#define TM     128          // == ghost-BN virtual batch
#define TN     128
#define KC     64           // K elems per chunk (fp16: 128B per row)
#define NCH    (DIM / KC)   // 32
#define NSTAGE 3
#define NTHR   256

// smem per-stage layout (bytes): fp16 tiles, 144B row stride (128B data + 16 pad)
#define ROWB   144
#define ST_A   0
#define ST_B   (ST_A + TM * ROWB)            // 18432
#define STAGE_SZ (ST_B + TN * ROWB)          // 36864
#define SMEM_TOTAL (NSTAGE * STAGE_SZ)       // 110592  (2 CTAs/SM: 221184 <= 228KB)

// epilogue staging (reuses pipeline smem): [128][130] fp32 + stats
#define C_STRIDE 130
#define C_BYTES  (TM * C_STRIDE * 4)         // 66560
#define OFF_SUM  C_BYTES                     // 256 floats
#define OFF_SQ   (OFF_SUM + 1024)            // 256 floats

// ---------------- scratch ----------------
__device__ float g_x[(size_t)BATCH * DIM];              // z = BN(x) * priors
__device__ uint2 g_a[(size_t)BATCH * DIM / 4];          // feat (fp16 x4)
__device__ uint2 g_b[(size_t)DIM * DIM / 4];            // W (fp16 x4)

// ---------------- helpers ----------------
__device__ __forceinline__ uint32_t smem_u32(const void* p) {
    uint32_t a;
    asm("{ .reg .u64 t; cvta.to.shared.u64 t, %1; cvt.u32.u64 %0, t; }" : "=r"(a) : "l"(p));
    return a;
}

__device__ __forceinline__ void ldsm_x4(uint32_t* r, uint32_t addr) {
    asm volatile("ldmatrix.sync.aligned.m8n8.x4.shared.b16 {%0,%1,%2,%3}, [%4];"
                 : "=r"(r[0]), "=r"(r[1]), "=r"(r[2]), "=r"(r[3]) : "r"(addr));
}

__device__ __forceinline__ void mma_f16(float* c, const uint32_t* a, uint32_t b0, uint32_t b1) {
    asm volatile("mma.sync.aligned.m16n8k16.row.col.f32.f16.f16.f32 "
                 "{%0,%1,%2,%3}, {%4,%5,%6,%7}, {%8,%9}, {%0,%1,%2,%3};"
                 : "+f"(c[0]), "+f"(c[1]), "+f"(c[2]), "+f"(c[3])
                 : "r"(a[0]), "r"(a[1]), "r"(a[2]), "r"(a[3]), "r"(b0), "r"(b1));
}

__device__ __forceinline__ void cp16(uint32_t dst, const void* src) {
    asm volatile("cp.async.cg.shared.global [%0], [%1], 16;" :: "r"(dst), "l"(src));
}
#define CP_COMMIT() asm volatile("cp.async.commit_group;" ::: "memory")
#define CP_WAIT1()  asm volatile("cp.async.wait_group 1;" ::: "memory")

__device__ __forceinline__ uint32_t h2u(__half2 h) {
    return *reinterpret_cast<uint32_t*>(&h);
}

// ================= kernel 0: fp32 -> fp16 RN =================
#define FEAT_N4 ((BATCH * DIM) / 4)
#define W_N4    ((DIM * DIM) / 4)

__global__ void __launch_bounds__(256)
split_kernel(const float* __restrict__ feat, const float* __restrict__ wmat)
{
    int idx = blockIdx.x * 256 + threadIdx.x;
    if (idx < FEAT_N4) {
        float4 v = reinterpret_cast<const float4*>(feat)[idx];
        g_a[idx] = make_uint2(h2u(__floats2half2_rn(v.x, v.y)), h2u(__floats2half2_rn(v.z, v.w)));
    } else if (idx < FEAT_N4 + W_N4) {
        int j = idx - FEAT_N4;
        float4 v = reinterpret_cast<const float4*>(wmat)[j];
        g_b[j] = make_uint2(h2u(__floats2half2_rn(v.x, v.y)), h2u(__floats2half2_rn(v.z, v.w)));
    }
}

// ================= kernel 1: GEMM (fp16) + fused GhostBN + x priors (R13 champion) =================
__global__ void __launch_bounds__(NTHR, 2)
gemm_bn_kernel(const float* __restrict__ gamma, const float* __restrict__ beta,
               const float* __restrict__ priors)
{
    extern __shared__ __align__(16) char smem[];
    const uint32_t sbase = smem_u32(smem);
    const int tid  = threadIdx.x;
    const int lane = tid & 31;
    const int wid  = tid >> 5;          // 0..7
    const int wm   = wid >> 2;          // warp row 0..1 (64 rows each)
    const int wn   = wid & 3;           // warp col 0..3 (32 cols each)
    const int m0   = blockIdx.y * TM;
    const int n0   = blockIdx.x * TN;

    // per-thread cp.async coordinates (16B chunks; 128B per tile row)
    const char* pA[4]; uint32_t dA[4];
    const char* pB[4]; uint32_t dB[4];
    #pragma unroll
    for (int i = 0; i < 4; ++i) {
        int item = tid + i * NTHR, r = item >> 3, q = item & 7;
        pA[i] = (const char*)g_a + ((size_t)(m0 + r) * DIM + q * 8) * 2;
        pB[i] = (const char*)g_b + ((size_t)(n0 + r) * DIM + q * 8) * 2;
        dA[i] = (uint32_t)(r * ROWB + q * 16);
        dB[i] = dA[i];
    }

    float acc[4][4][4];
    #pragma unroll
    for (int i = 0; i < 4; ++i)
        #pragma unroll
        for (int j = 0; j < 4; ++j)
            #pragma unroll
            for (int k = 0; k < 4; ++k) acc[i][j][k] = 0.f;

    // per-lane ldmatrix offsets (within a stage)
    const uint32_t a_off = (uint32_t)((wm * 64 + (lane & 15)) * ROWB + (lane >> 4) * 16);
    const uint32_t b_off = (uint32_t)((wn * 32 + (lane & 7) + ((lane >> 4) & 1) * 8) * ROWB
                                      + ((lane >> 3) & 1) * 16);

    // prologue: stages 0,1 in flight
    #pragma unroll
    for (int s = 0; s < 2; ++s) {
        const size_t kb = (size_t)(s * KC) * 2;   // byte offset along K
        const uint32_t sb = sbase + s * STAGE_SZ;
        #pragma unroll
        for (int i = 0; i < 4; ++i) cp16(sb + ST_A + dA[i], pA[i] + kb);
        #pragma unroll
        for (int i = 0; i < 4; ++i) cp16(sb + ST_B + dB[i], pB[i] + kb);
        CP_COMMIT();
    }

    int s_cur = 0, s_nxt = 2;
    for (int c = 0; c < NCH; ++c) {
        CP_WAIT1();
        __syncthreads();                          // stage s_cur ready; stage s_nxt free

        if (c + 2 < NCH) {
            const size_t kb = (size_t)((c + 2) * KC) * 2;
            const uint32_t sb = sbase + s_nxt * STAGE_SZ;
            #pragma unroll
            for (int i = 0; i < 4; ++i) cp16(sb + ST_A + dA[i], pA[i] + kb);
            #pragma unroll
            for (int i = 0; i < 4; ++i) cp16(sb + ST_B + dB[i], pB[i] + kb);
        }
        CP_COMMIT();

        const uint32_t st = sbase + s_cur * STAGE_SZ;
        #pragma unroll
        for (int ks = 0; ks < 4; ++ks) {
            const uint32_t kb = (uint32_t)(ks * 32);
            uint32_t af[4][4], bb[2][4];
            #pragma unroll
            for (int mt = 0; mt < 4; ++mt) ldsm_x4(af[mt], st + ST_A + a_off + mt * (16 * ROWB) + kb);
            #pragma unroll
            for (int bt = 0; bt < 2; ++bt) ldsm_x4(bb[bt], st + ST_B + b_off + bt * (16 * ROWB) + kb);
            #pragma unroll
            for (int mt = 0; mt < 4; ++mt)
                #pragma unroll
                for (int nt = 0; nt < 4; ++nt)
                    mma_f16(acc[mt][nt], af[mt], bb[nt >> 1][(nt & 1) * 2], bb[nt >> 1][(nt & 1) * 2 + 1]);
        }
        s_cur = (s_cur + 1) % NSTAGE;
        s_nxt = (s_nxt + 1) % NSTAGE;
    }
    __syncthreads();    // pipeline smem free; reuse for epilogue

    // ---- stage C tile to smem ----
    float* sf = reinterpret_cast<float*>(smem);           // [128][130]
    {
        const int rbase = wm * 64 + (lane >> 2);
        const int cbase = wn * 32 + (lane & 3) * 2;
        #pragma unroll
        for (int mt = 0; mt < 4; ++mt)
            #pragma unroll
            for (int nt = 0; nt < 4; ++nt) {
                int r = rbase + mt * 16, cc = cbase + nt * 8;
                *reinterpret_cast<float2*>(&sf[r * C_STRIDE + cc]) =
                    make_float2(acc[mt][nt][0], acc[mt][nt][1]);
                *reinterpret_cast<float2*>(&sf[(r + 8) * C_STRIDE + cc]) =
                    make_float2(acc[mt][nt][2], acc[mt][nt][3]);
            }
    }
    __syncthreads();

    // ---- ghost-BN stats over the 128-row tile (per column) ----
    float* s_sum = reinterpret_cast<float*>(smem + OFF_SUM);          // [256]
    float* s_sq  = reinterpret_cast<float*>(smem + OFF_SQ);           // [256]
    {
        const int col = tid & 127, part = tid >> 7;       // 2 partitions x 64 rows
        float sum = 0.f, sq = 0.f;
        #pragma unroll 8
        for (int r = part * 64; r < part * 64 + 64; ++r) {
            float v = sf[r * C_STRIDE + col];
            sum += v; sq += v * v;
        }
        s_sum[tid] = sum; s_sq[tid] = sq;
    }
    __syncthreads();
    if (tid < 128) {
        float sum = s_sum[tid] + s_sum[tid + 128];
        float sq  = s_sq[tid] + s_sq[tid + 128];
        float mean = sum * (1.f / 128.f);
        float var  = fmaxf(sq * (1.f / 128.f) - mean * mean, 0.f);
        float sc = gamma[n0 + tid] * rsqrtf(var + 1e-5f);
        s_sum[tid] = sc;                         // scale
        s_sq[tid]  = beta[n0 + tid] - mean * sc; // shift
    }
    __syncthreads();

    // ---- normalized write x priors (float4) ----
    float* orow = g_x + (size_t)m0 * DIM + n0;
    const float* prow = priors + (size_t)m0 * DIM + n0;
    #pragma unroll
    for (int i = 0; i < 16; ++i) {
        int idx = tid + i * NTHR;                // 4096 float4s
        int r = idx >> 5, c4 = (idx & 31) * 4;
        float4 p = *reinterpret_cast<const float4*>(&prow[(size_t)r * DIM + c4]);
        float4 v;
        v.x = (sf[r * C_STRIDE + c4 + 0] * s_sum[c4 + 0] + s_sq[c4 + 0]) * p.x;
        v.y = (sf[r * C_STRIDE + c4 + 1] * s_sum[c4 + 1] + s_sq[c4 + 1]) * p.y;
        v.z = (sf[r * C_STRIDE + c4 + 2] * s_sum[c4 + 2] + s_sq[c4 + 2]) * p.z;
        v.w = (sf[r * C_STRIDE + c4 + 3] * s_sum[c4 + 3] + s_sq[c4 + 3]) * p.w;
        *reinterpret_cast<float4*>(&orow[(size_t)r * DIM + c4]) = v;
    }
}

// ================= kernel 2: sparsemax (warp-per-row Michelot, streaming I/O) =================
__device__ __forceinline__ float warp_sum(float v) {
    #pragma unroll
    for (int o = 16; o > 0; o >>= 1) v += __shfl_xor_sync(0xffffffffu, v, o);
    return v;
}
__device__ __forceinline__ float warp_max(float v) {
    #pragma unroll
    for (int o = 16; o > 0; o >>= 1) v = fmaxf(v, __shfl_xor_sync(0xffffffffu, v, o));
    return v;
}

__global__ void __launch_bounds__(256)
sparsemax_kernel(float* __restrict__ out)
{
    const int lane = threadIdx.x & 31;
    const int row  = blockIdx.x * 8 + (threadIdx.x >> 5);
    const float4* x4 = reinterpret_cast<const float4*>(g_x + (size_t)row * DIM);

    float z[64];
    float s = 0.f, mx = -1e30f;
    #pragma unroll
    for (int i = 0; i < 16; ++i) {
        float4 a = __ldcs(&x4[lane + i * 32]);    // single-touch: evict-first
        z[i * 4 + 0] = a.x; z[i * 4 + 1] = a.y; z[i * 4 + 2] = a.z; z[i * 4 + 3] = a.w;
        s += a.x + a.y + a.z + a.w;
        mx = fmaxf(mx, fmaxf(fmaxf(a.x, a.y), fmaxf(a.z, a.w)));
    }
    s  = warp_sum(s);
    mx = warp_max(mx);
    // warm start: tau* in [max-1, max-1/D]; both candidates are valid lower bounds
    float tau = fmaxf(mx - 1.f, (s - 1.f) * (1.f / (float)DIM));

    for (int it = 0; it < 32; ++it) {
        float ps = 0.f, pc = 0.f;
        #pragma unroll
        for (int i = 0; i < 64; ++i)
            if (z[i] > tau) { ps += z[i]; pc += 1.f; }
        ps = warp_sum(ps); pc = warp_sum(pc);
        float tn = (ps - 1.f) / pc;
        if (tn == tau) break;        // warp-uniform (same reduced values)
        tau = tn;
    }

    float4* o4 = reinterpret_cast<float4*>(out + (size_t)row * DIM);
    #pragma unroll
    for (int i = 0; i < 16; ++i) {
        float4 v;
        v.x = fmaxf(z[i * 4 + 0] - tau, 0.f);
        v.y = fmaxf(z[i * 4 + 1] - tau, 0.f);
        v.z = fmaxf(z[i * 4 + 2] - tau, 0.f);
        v.w = fmaxf(z[i * 4 + 3] - tau, 0.f);
        __stcs(&o4[lane + i * 32], v);            // streaming store
    }
}

// ================= launch =================
extern "C" void kernel_launch(void* const* d_in, const int* in_sizes, int n_in,
                              void* d_out, int out_size)
{
    const float* priors = (const float*)d_in[0];
    const float* feat   = (const float*)d_in[1];
    const float* fw     = (const float*)d_in[2];
    const float* gamma  = (const float*)d_in[3];
    const float* beta   = (const float*)d_in[4];
    float* out = (float*)d_out;

    static bool attr_set = false;
    if (!attr_set) {
        cudaFuncSetAttribute(gemm_bn_kernel, cudaFuncAttributeMaxDynamicSharedMemorySize, SMEM_TOTAL);
        attr_set = true;
    }

    split_kernel<<<(FEAT_N4 + W_N4 + 255) / 256, 256>>>(feat, fw);
    dim3 grid(DIM / TN, BATCH / TM);    // (16, 128); x fastest keeps W in L2
    gemm_bn_kernel<<<grid, NTHR, SMEM_TOTAL>>>(gamma, beta, priors);
    sparsemax_kernel<<<BATCH / 8, 256>>>(out);
}